// round 14
// baseline (speedup 1.0000x reference)
#include <cuda_runtime.h>

// MinimalPhysicsModel: 50-step recurrent sim + MLP(11->64->64->2, tanh).
// S=4 lanes/slot, E=4 elements/slot. Interleaved quad ownership: every weight
// LDS.128 request is 64B-contiguous; transposed h staging: every layer-2 h
// load is a 128B-contiguous broadcast. Linear-prefetch pipeline, SMEM feature
// broadcast, fast atan2.
// R14: TPB=96, launch_bounds(96,5) -> 136-reg budget, 15 warps/SM (vs 12).
// SMEM shrunk to 46.2KB/block (H_R=100, feature buffer aliased into h rows
// 54..64; safe: cross-warp accesses are column-partitioned, in-warp f reads
// precede h stores, pad-row prefetch data never consumed).

#define STEPS   50
#define HID     64
#define NFEAT   11
#define EPS_F   1e-6f
#define DT_F    (1.0f/30.0f)
#define TPB     96
#define ELEMS_PER_CTA 96

typedef unsigned long long u64;

__device__ __forceinline__ u64 pk2(float x, float y) {
    u64 r; asm("mov.b64 %0,{%1,%2};" : "=l"(r) : "f"(x), "f"(y)); return r;
}
__device__ __forceinline__ void upk2(u64 v, float& x, float& y) {
    asm("mov.b64 {%0,%1},%2;" : "=f"(x), "=f"(y) : "l"(v));
}
__device__ __forceinline__ u64 ffma2(u64 a, u64 b, u64 c) {
    u64 d; asm("fma.rn.f32x2 %0,%1,%2,%3;" : "=l"(d) : "l"(a), "l"(b), "l"(c)); return d;
}

// tanh(x) = 1 - 2/(1 + e^{2x});  sign-correct, inf-safe, 5 ops, |err| ~1e-7.
__device__ __forceinline__ float tanh_fast(float x) {
    float e;
    asm("ex2.approx.f32 %0, %1;" : "=f"(e) : "f"(x * 2.885390082f)); // 2*log2(e)
    float rc;
    asm("rcp.approx.f32 %0, %1;" : "=f"(rc) : "f"(1.0f + e));
    return fmaf(-2.0f, rc, 1.0f);
}

__device__ __forceinline__ float sqrt_fast(float x) {
    float r;
    asm("sqrt.approx.f32 %0, %1;" : "=f"(r) : "f"(x));
    return r;
}

// atan2 via degree-11 odd minimax on [0,1] + octant fixups; |err| ~2e-7.
__device__ __forceinline__ float atan2_fast(float y, float x) {
    float ax = fabsf(x), ay = fabsf(y);
    float mx = fmaxf(ax, ay), mn = fminf(ax, ay);
    float r  = __fdividef(mn, mx);
    float q  = r * r;
    float p  = fmaf(q, -0.0117212f,  0.05265332f);
    p = fmaf(q, p, -0.11643287f);
    p = fmaf(q, p,  0.19354346f);
    p = fmaf(q, p, -0.33262347f);
    p = fmaf(q, p,  0.99997726f);
    float a = r * p;
    a = (ay > ax) ? (1.57079632679f - a) : a;
    a = (x < 0.0f) ? (3.14159265359f - a) : a;
    return copysignf(a, y);
}

// shared layout (floats)
#define OFF_W1  0        // 11*64 = 704
#define OFF_B1  704      // 64
#define OFF_W2  768      // 64*64 = 4096
#define OFF_B2  4864     // 64
#define OFF_W3  4928     // 64*2 = 128
#define OFF_B3  5056     // 2
#define OFF_H   5060     // h2[65][100]: 64 rows + 1 pad row (prefetch overrun)
#define H_R     100      // 96 elems + pad 4 (row delta mod 128B = 64: no store conflicts)
#define OFF_F   (OFF_H + 54 * H_R)              // f2[11][100] ALIASED into h rows 54..64
#define SM_FLOATS (OFF_H + 65 * H_R)            // 5060 + 6500 = 11560
#define SM_BYTES  (SM_FLOATS * 4)               // 46240  (x5 = 231.2KB/SM, fits 233.5KB)

__global__ void __launch_bounds__(TPB, 5)
phys_kernel(const float* __restrict__ inp,
            const float* __restrict__ W1, const float* __restrict__ b1,
            const float* __restrict__ W2, const float* __restrict__ b2,
            const float* __restrict__ W3, const float* __restrict__ b3,
            const float* __restrict__ grav, const float* __restrict__ fricp,
            float* __restrict__ out, int nB)
{
    extern __shared__ __align__(16) float sm[];
    int tid = threadIdx.x;

    for (int i = tid; i < 704;  i += TPB) sm[OFF_W1 + i] = W1[i];
    for (int i = tid; i < 64;   i += TPB) sm[OFF_B1 + i] = b1[i];
    for (int i = tid; i < 4096; i += TPB) sm[OFF_W2 + i] = W2[i];
    for (int i = tid; i < 64;   i += TPB) sm[OFF_B2 + i] = b2[i];
    for (int i = tid; i < 128;  i += TPB) sm[OFF_W3 + i] = W3[i];
    if (tid == 0) { sm[OFF_B3] = b3[0]; sm[OFF_B3 + 1] = b3[1]; }
    __syncthreads();

    const int l      = tid & 3;            // owns row-quads {l, l+4, l+8, l+12}
    const int leBase = tid & ~3;           // CTA-local element base of this slot

    int myE = (blockIdx.x * (ELEMS_PER_CTA / 4) + (tid >> 2)) * 4 + l;
    if (myE >= nB) myE = nB - 1;           // dup-safe (identical writes)

    float p1x, p1y, p2x, p2y, v1x, v1y, v2x, v2y;
    {
        const float* s0 = inp + (size_t)myE * STEPS * 8;
        float4 a = *(const float4*)(s0);
        float4 b = *(const float4*)(s0 + 4);
        p1x = a.x; p1y = a.y; p2x = a.z; p2y = a.w;
        v1x = b.x; v1y = b.y; v2x = b.z; v2y = b.w;
    }

    float g    = grav[0] * 40.0f;
    float fric = fabsf(fricp[0]);

    float* ob = out + (size_t)myE * STEPS * 8;

    // lane-hoisted base pointers
    const ulonglong2* W1l  = (const ulonglong2*)(sm + OFF_W1) + l;     // [11][16]
    const ulonglong2* B1l  = (const ulonglong2*)(sm + OFF_B1) + l;     // [16]
    const ulonglong2* W2l  = (const ulonglong2*)(sm + OFF_W2) + l;     // [64][16]
    const ulonglong2* B2l  = (const ulonglong2*)(sm + OFF_B2) + l;     // [16]
    const ulonglong2* W3l  = (const ulonglong2*)(sm + OFF_W3) + 2 * l; // [32]
    const float*      hbl  = sm + OFF_H + leBase;
    float*            hbsl = sm + OFF_H + leBase;
    const float*      fbl  = sm + OFF_F + leBase;
    float*            fbs  = sm + OFF_F + tid;    // own element's feature column

    const unsigned FULL = 0xffffffffu;

#pragma unroll 1
    for (int t = 0; t < STEPS; t++) {
        *(float4*)(ob)     = make_float4(p1x, p1y, p2x, p2y);
        *(float4*)(ob + 4) = make_float4(v1x, v1y, v2x, v2y);
        ob += 8;

        // ---- features for own element -> SMEM transposed columns ----
        {
            float s1  = p1x * p1x + p1y * p1y;      // = r1^2
            float r1  = sqrt_fast(s1);
            float th1 = atan2_fast(p1y, p1x);
            float vr1 = __fdividef(p1x * v1x + p1y * v1y, r1 + EPS_F);
            float vt1 = __fdividef(p1x * v1y - p1y * v1x, s1 + EPS_F);
            float L1  = r1 * vt1;

            float s2  = p2x * p2x + p2y * p2y;      // = r2^2
            float r2  = sqrt_fast(s2);
            float th2 = atan2_fast(p2y, p2x);
            float vr2 = __fdividef(p2x * v2x + p2y * v2y, r2 + EPS_F);
            float vt2 = __fdividef(p2x * v2y - p2y * v2x, s2 + EPS_F);
            float L2  = r2 * vt2;

            float dx = p2x - p1x, dy = p2y - p1y;
            float r12 = sqrt_fast(dx * dx + dy * dy);

            fbs[0 * H_R]  = r1;  fbs[1 * H_R] = th1; fbs[2 * H_R] = vr1;
            fbs[3 * H_R]  = vt1; fbs[4 * H_R] = L1;  fbs[5 * H_R] = r2;
            fbs[6 * H_R]  = th2; fbs[7 * H_R] = vr2; fbs[8 * H_R] = vt2;
            fbs[9 * H_R]  = L2;  fbs[10 * H_R] = r12;
        }
        __syncwarp();

        // ---- layer 1: own 16 hidden units (interleaved quads) x 4 elems ----
        {
            u64 a1[4][8];
#pragma unroll
            for (int gq = 0; gq < 4; gq++) {
                ulonglong2 bq = B1l[4 * gq];
#pragma unroll
                for (int e = 0; e < 4; e++) {
                    a1[e][2 * gq]     = bq.x;
                    a1[e][2 * gq + 1] = bq.y;
                }
            }

#pragma unroll
            for (int i = 0; i < NFEAT; i++) {
                float4 fv = *(const float4*)(fbl + i * H_R);   // 128B bcast, 1 wf
                u64 fe[4];
                fe[0] = pk2(fv.x, fv.x);
                fe[1] = pk2(fv.y, fv.y);
                fe[2] = pk2(fv.z, fv.z);
                fe[3] = pk2(fv.w, fv.w);
#pragma unroll
                for (int gq = 0; gq < 4; gq++) {
                    ulonglong2 w = W1l[i * 16 + 4 * gq];   // 64B-contig request
#pragma unroll
                    for (int e = 0; e < 4; e++) {
                        a1[e][2 * gq]     = ffma2(fe[e], w.x, a1[e][2 * gq]);
                        a1[e][2 * gq + 1] = ffma2(fe[e], w.y, a1[e][2 * gq + 1]);
                    }
                }
            }

            // tanh + transposed store: h2[u][elem], u = 16*gq + 4*l + j
            // (h stores to rows 54..63 overwrite the f alias region — f is
            //  fully consumed above; cross-warp columns are disjoint.)
#pragma unroll
            for (int gq = 0; gq < 4; gq++) {
                float tq[4][4];
#pragma unroll
                for (int e = 0; e < 4; e++) {
                    float x0, x1, x2, x3;
                    upk2(a1[e][2 * gq],     x0, x1);
                    upk2(a1[e][2 * gq + 1], x2, x3);
                    tq[e][0] = tanh_fast(x0);
                    tq[e][1] = tanh_fast(x1);
                    tq[e][2] = tanh_fast(x2);
                    tq[e][3] = tanh_fast(x3);
                }
#pragma unroll
                for (int j = 0; j < 4; j++) {
                    int u = 16 * gq + 4 * l + j;
                    *(float4*)(hbsl + u * H_R) =
                        make_float4(tq[0][j], tq[1][j], tq[2][j], tq[3][j]);
                }
            }
        }
        __syncwarp();

        // ---- layer 2: own 16 units over all 64 hidden, 4 elems ----
        // 2-stage pipeline with LINEAR prefetch; k=63 prefetch hits pad row 64
        // (stale f data, never consumed).
        u64 a2[4][8];
#pragma unroll
        for (int gq = 0; gq < 4; gq++) {
            ulonglong2 bq = B2l[4 * gq];
#pragma unroll
            for (int e = 0; e < 4; e++) {
                a2[e][2 * gq]     = bq.x;
                a2[e][2 * gq + 1] = bq.y;
            }
        }

        const float*      hp = hbl;
        const ulonglong2* Wp = W2l;
        float4     hv_n = *(const float4*)hp;
        ulonglong2 wn0  = Wp[0];
        ulonglong2 wn1  = Wp[4];
        ulonglong2 wn2  = Wp[8];
        ulonglong2 wn3  = Wp[12];

#pragma unroll 8
        for (int k = 0; k < HID; k++) {
            float4     hv = hv_n;
            ulonglong2 w0 = wn0, w1 = wn1, w2 = wn2, w3 = wn3;

            hp += H_R;
            Wp += 16;
            hv_n = *(const float4*)hp;
            wn0 = Wp[0]; wn1 = Wp[4]; wn2 = Wp[8]; wn3 = Wp[12];

            u64 hk0 = pk2(hv.x, hv.x);
            u64 hk1 = pk2(hv.y, hv.y);
            u64 hk2 = pk2(hv.z, hv.z);
            u64 hk3 = pk2(hv.w, hv.w);

            a2[0][0] = ffma2(hk0, w0.x, a2[0][0]);
            a2[0][1] = ffma2(hk0, w0.y, a2[0][1]);
            a2[1][0] = ffma2(hk1, w0.x, a2[1][0]);
            a2[1][1] = ffma2(hk1, w0.y, a2[1][1]);
            a2[2][0] = ffma2(hk2, w0.x, a2[2][0]);
            a2[2][1] = ffma2(hk2, w0.y, a2[2][1]);
            a2[3][0] = ffma2(hk3, w0.x, a2[3][0]);
            a2[3][1] = ffma2(hk3, w0.y, a2[3][1]);

            a2[0][2] = ffma2(hk0, w1.x, a2[0][2]);
            a2[0][3] = ffma2(hk0, w1.y, a2[0][3]);
            a2[1][2] = ffma2(hk1, w1.x, a2[1][2]);
            a2[1][3] = ffma2(hk1, w1.y, a2[1][3]);
            a2[2][2] = ffma2(hk2, w1.x, a2[2][2]);
            a2[2][3] = ffma2(hk2, w1.y, a2[2][3]);
            a2[3][2] = ffma2(hk3, w1.x, a2[3][2]);
            a2[3][3] = ffma2(hk3, w1.y, a2[3][3]);

            a2[0][4] = ffma2(hk0, w2.x, a2[0][4]);
            a2[0][5] = ffma2(hk0, w2.y, a2[0][5]);
            a2[1][4] = ffma2(hk1, w2.x, a2[1][4]);
            a2[1][5] = ffma2(hk1, w2.y, a2[1][5]);
            a2[2][4] = ffma2(hk2, w2.x, a2[2][4]);
            a2[2][5] = ffma2(hk2, w2.y, a2[2][5]);
            a2[3][4] = ffma2(hk3, w2.x, a2[3][4]);
            a2[3][5] = ffma2(hk3, w2.y, a2[3][5]);

            a2[0][6] = ffma2(hk0, w3.x, a2[0][6]);
            a2[0][7] = ffma2(hk0, w3.y, a2[0][7]);
            a2[1][6] = ffma2(hk1, w3.x, a2[1][6]);
            a2[1][7] = ffma2(hk1, w3.y, a2[1][7]);
            a2[2][6] = ffma2(hk2, w3.x, a2[2][6]);
            a2[2][7] = ffma2(hk2, w3.y, a2[2][7]);
            a2[3][6] = ffma2(hk3, w3.x, a2[3][6]);
            a2[3][7] = ffma2(hk3, w3.y, a2[3][7]);
        }
        __syncwarp();

        // ---- layer 3: partial dot over own 16 units, per element ----
        u64 c[4], d[4];
        {
            u64 binit = (l == 0) ? pk2(sm[OFF_B3], sm[OFF_B3 + 1]) : pk2(0.0f, 0.0f);
#pragma unroll
            for (int e = 0; e < 4; e++) { c[e] = binit; d[e] = pk2(0.0f, 0.0f); }
#pragma unroll
            for (int gq = 0; gq < 4; gq++) {
                ulonglong2 wA = W3l[8 * gq];
                ulonglong2 wB = W3l[8 * gq + 1];
#pragma unroll
                for (int e = 0; e < 4; e++) {
                    float x0, x1, x2, x3;
                    upk2(a2[e][2 * gq],     x0, x1);
                    upk2(a2[e][2 * gq + 1], x2, x3);
                    float g0 = tanh_fast(x0), g1 = tanh_fast(x1);
                    float g2 = tanh_fast(x2), g3 = tanh_fast(x3);
                    c[e] = ffma2(pk2(g0, g0), wA.x, c[e]);
                    d[e] = ffma2(pk2(g1, g1), wA.y, d[e]);
                    c[e] = ffma2(pk2(g2, g2), wB.x, c[e]);
                    d[e] = ffma2(pk2(g3, g3), wB.y, d[e]);
                }
            }
        }

        // butterfly-reduce each element's partial across the 4 slot lanes
        float corrx = 0.0f, corry = 0.0f;
#pragma unroll
        for (int e = 0; e < 4; e++) {
            float x0, y0, x1, y1;
            upk2(c[e], x0, y0); upk2(d[e], x1, y1);
            float sx = x0 + x1, sy = y0 + y1;
            float u;
            u = __shfl_xor_sync(FULL, sx, 1); sx = sx + u;   // commutative: identical on all lanes
            u = __shfl_xor_sync(FULL, sx, 2); sx = sx + u;
            u = __shfl_xor_sync(FULL, sy, 1); sy = sy + u;
            u = __shfl_xor_sync(FULL, sy, 2); sy = sy + u;
            if (e == l) { corrx = sx * 0.1f; corry = sy * 0.1f; }
        }

        // ---- integrate own element ----
        float a1x = corrx - fric * v1x;
        float a1y = g + corry - fric * v1y;
        float a2x = corrx - fric * v2x;
        float a2y = g + corry - fric * v2y;

        v1x += a1x * DT_F;  v1y += a1y * DT_F;
        v2x += a2x * DT_F;  v2y += a2y * DT_F;
        p1x += v1x * DT_F;  p1y += v1y * DT_F;
        p2x += v2x * DT_F;  p2y += v2y * DT_F;

        bool m;
        m = (p1x < 20.0f) || (p1x > 780.0f); v1x = m ? -0.8f * v1x : v1x;
        p1x = fminf(fmaxf(p1x, 20.0f), 780.0f);
        m = (p1y < 20.0f) || (p1y > 580.0f); v1y = m ? -0.8f * v1y : v1y;
        p1y = fminf(fmaxf(p1y, 20.0f), 580.0f);

        m = (p2x < 20.0f) || (p2x > 780.0f); v2x = m ? -0.8f * v2x : v2x;
        p2x = fminf(fmaxf(p2x, 20.0f), 780.0f);
        m = (p2y < 20.0f) || (p2y > 580.0f); v2y = m ? -0.8f * v2y : v2y;
        p2y = fminf(fmaxf(p2y, 20.0f), 580.0f);
    }
}

extern "C" void kernel_launch(void* const* d_in, const int* in_sizes, int n_in,
                              void* d_out, int out_size) {
    const float* inp  = (const float*)d_in[0];
    const float* W1   = (const float*)d_in[1];
    const float* b1   = (const float*)d_in[2];
    const float* W2   = (const float*)d_in[3];
    const float* b2   = (const float*)d_in[4];
    const float* W3   = (const float*)d_in[5];
    const float* b3   = (const float*)d_in[6];
    const float* grav = (const float*)d_in[7];
    const float* fric = (const float*)d_in[8];
    float* out = (float*)d_out;

    int nB = in_sizes[0] / (STEPS * 8);

    static int smem_set = 0;
    if (!smem_set) {
        cudaFuncSetAttribute(phys_kernel,
                             cudaFuncAttributeMaxDynamicSharedMemorySize, SM_BYTES);
        smem_set = 1;
    }

    int nElems = ((nB + ELEMS_PER_CTA - 1) / ELEMS_PER_CTA) * ELEMS_PER_CTA;
    int grid   = nElems / ELEMS_PER_CTA;
    phys_kernel<<<grid, TPB, SM_BYTES>>>(inp, W1, b1, W2, b2, W3, b3,
                                         grav, fric, out, nB);
}

// round 15
// speedup vs baseline: 1.0169x; 1.0169x over previous
#include <cuda_runtime.h>

// MinimalPhysicsModel: 50-step recurrent sim + MLP(11->64->64->2, tanh).
// S=4 lanes/slot, E=4 elements/slot. Interleaved quad ownership: every weight
// LDS.128 request is 64B-contiguous; transposed h staging: every layer-2 h
// load is a 128B-contiguous broadcast. Linear-prefetch pipeline, SMEM feature
// broadcast, fast atan2.  (= R13 config: TPB=128, 3 blocks/SM, 168 regs)
// R15: layer-3 epilogue switched from redundant all-lane butterfly (16 SHFL)
// to 2-stage transpose-reduce (6 SHFL) — each lane computes only its own
// element's correction. Everything else identical to R13.

#define STEPS   50
#define HID     64
#define NFEAT   11
#define EPS_F   1e-6f
#define DT_F    (1.0f/30.0f)
#define TPB     128

typedef unsigned long long u64;

__device__ __forceinline__ u64 pk2(float x, float y) {
    u64 r; asm("mov.b64 %0,{%1,%2};" : "=l"(r) : "f"(x), "f"(y)); return r;
}
__device__ __forceinline__ void upk2(u64 v, float& x, float& y) {
    asm("mov.b64 {%0,%1},%2;" : "=f"(x), "=f"(y) : "l"(v));
}
__device__ __forceinline__ u64 ffma2(u64 a, u64 b, u64 c) {
    u64 d; asm("fma.rn.f32x2 %0,%1,%2,%3;" : "=l"(d) : "l"(a), "l"(b), "l"(c)); return d;
}

// tanh(x) = 1 - 2/(1 + e^{2x});  sign-correct, inf-safe, 5 ops, |err| ~1e-7.
__device__ __forceinline__ float tanh_fast(float x) {
    float e;
    asm("ex2.approx.f32 %0, %1;" : "=f"(e) : "f"(x * 2.885390082f)); // 2*log2(e)
    float rc;
    asm("rcp.approx.f32 %0, %1;" : "=f"(rc) : "f"(1.0f + e));
    return fmaf(-2.0f, rc, 1.0f);
}

__device__ __forceinline__ float sqrt_fast(float x) {
    float r;
    asm("sqrt.approx.f32 %0, %1;" : "=f"(r) : "f"(x));
    return r;
}

// atan2 via degree-11 odd minimax on [0,1] + octant fixups; |err| ~2e-7.
__device__ __forceinline__ float atan2_fast(float y, float x) {
    float ax = fabsf(x), ay = fabsf(y);
    float mx = fmaxf(ax, ay), mn = fminf(ax, ay);
    float r  = __fdividef(mn, mx);
    float q  = r * r;
    float p  = fmaf(q, -0.0117212f,  0.05265332f);
    p = fmaf(q, p, -0.11643287f);
    p = fmaf(q, p,  0.19354346f);
    p = fmaf(q, p, -0.33262347f);
    p = fmaf(q, p,  0.99997726f);
    float a = r * p;
    a = (ay > ax) ? (1.57079632679f - a) : a;
    a = (x < 0.0f) ? (3.14159265359f - a) : a;
    return copysignf(a, y);
}

// shared layout (floats)
#define OFF_W1  0        // 11*64 = 704
#define OFF_B1  704      // 64
#define OFF_W2  768      // 64*64 = 4096
#define OFF_B2  4864     // 64
#define OFF_W3  4928     // 64*2 = 128
#define OFF_B3  5056     // 2
#define OFF_H   5060     // h2[65][132]: 64 rows + 1 pad row (prefetch overrun)
#define H_R     132
#define OFF_F   (OFF_H + 65 * H_R)              // f2[11][132]
#define SM_FLOATS (OFF_F + NFEAT * H_R)         // 15092
#define SM_BYTES  (SM_FLOATS * 4)               // 60368  (x3 = 181KB/SM)

__global__ void __launch_bounds__(TPB, 3)
phys_kernel(const float* __restrict__ inp,
            const float* __restrict__ W1, const float* __restrict__ b1,
            const float* __restrict__ W2, const float* __restrict__ b2,
            const float* __restrict__ W3, const float* __restrict__ b3,
            const float* __restrict__ grav, const float* __restrict__ fricp,
            float* __restrict__ out, int nB)
{
    extern __shared__ __align__(16) float sm[];
    int tid = threadIdx.x;

    for (int i = tid; i < 704;  i += TPB) sm[OFF_W1 + i] = W1[i];
    for (int i = tid; i < 64;   i += TPB) sm[OFF_B1 + i] = b1[i];
    for (int i = tid; i < 4096; i += TPB) sm[OFF_W2 + i] = W2[i];
    for (int i = tid; i < 64;   i += TPB) sm[OFF_B2 + i] = b2[i];
    for (int i = tid; i < 128;  i += TPB) sm[OFF_W3 + i] = W3[i];
    if (tid == 0) { sm[OFF_B3] = b3[0]; sm[OFF_B3 + 1] = b3[1]; }
    __syncthreads();

    const int l      = tid & 3;            // owns row-quads {l, l+4, l+8, l+12}
    const int leBase = tid & ~3;           // CTA-local element base of this slot
    const int par    = l & 1;              // parity bit
    const int hib    = (l >> 1) & 1;       // high bit

    int myE = (blockIdx.x * 32 + (tid >> 2)) * 4 + l;
    if (myE >= nB) myE = nB - 1;           // dup-safe (identical writes)

    float p1x, p1y, p2x, p2y, v1x, v1y, v2x, v2y;
    {
        const float* s0 = inp + (size_t)myE * STEPS * 8;
        float4 a = *(const float4*)(s0);
        float4 b = *(const float4*)(s0 + 4);
        p1x = a.x; p1y = a.y; p2x = a.z; p2y = a.w;
        v1x = b.x; v1y = b.y; v2x = b.z; v2y = b.w;
    }

    float g    = grav[0] * 40.0f;
    float fric = fabsf(fricp[0]);

    float* ob = out + (size_t)myE * STEPS * 8;

    // lane-hoisted base pointers
    const ulonglong2* W1l  = (const ulonglong2*)(sm + OFF_W1) + l;     // [11][16]
    const ulonglong2* B1l  = (const ulonglong2*)(sm + OFF_B1) + l;     // [16]
    const ulonglong2* W2l  = (const ulonglong2*)(sm + OFF_W2) + l;     // [64][16]
    const ulonglong2* B2l  = (const ulonglong2*)(sm + OFF_B2) + l;     // [16]
    const ulonglong2* W3l  = (const ulonglong2*)(sm + OFF_W3) + 2 * l; // [32]
    const float*      hbl  = sm + OFF_H + leBase;
    float*            hbsl = sm + OFF_H + leBase;
    const float*      fbl  = sm + OFF_F + leBase;
    float*            fbs  = sm + OFF_F + tid;    // own element's feature column

    const unsigned FULL = 0xffffffffu;

#pragma unroll 1
    for (int t = 0; t < STEPS; t++) {
        *(float4*)(ob)     = make_float4(p1x, p1y, p2x, p2y);
        *(float4*)(ob + 4) = make_float4(v1x, v1y, v2x, v2y);
        ob += 8;

        // ---- features for own element -> SMEM transposed columns ----
        {
            float s1  = p1x * p1x + p1y * p1y;      // = r1^2
            float r1  = sqrt_fast(s1);
            float th1 = atan2_fast(p1y, p1x);
            float vr1 = __fdividef(p1x * v1x + p1y * v1y, r1 + EPS_F);
            float vt1 = __fdividef(p1x * v1y - p1y * v1x, s1 + EPS_F);
            float L1  = r1 * vt1;

            float s2  = p2x * p2x + p2y * p2y;      // = r2^2
            float r2  = sqrt_fast(s2);
            float th2 = atan2_fast(p2y, p2x);
            float vr2 = __fdividef(p2x * v2x + p2y * v2y, r2 + EPS_F);
            float vt2 = __fdividef(p2x * v2y - p2y * v2x, s2 + EPS_F);
            float L2  = r2 * vt2;

            float dx = p2x - p1x, dy = p2y - p1y;
            float r12 = sqrt_fast(dx * dx + dy * dy);

            fbs[0 * H_R]  = r1;  fbs[1 * H_R] = th1; fbs[2 * H_R] = vr1;
            fbs[3 * H_R]  = vt1; fbs[4 * H_R] = L1;  fbs[5 * H_R] = r2;
            fbs[6 * H_R]  = th2; fbs[7 * H_R] = vr2; fbs[8 * H_R] = vt2;
            fbs[9 * H_R]  = L2;  fbs[10 * H_R] = r12;
        }
        __syncwarp();

        // ---- layer 1: own 16 hidden units (interleaved quads) x 4 elems ----
        {
            u64 a1[4][8];
#pragma unroll
            for (int gq = 0; gq < 4; gq++) {
                ulonglong2 bq = B1l[4 * gq];
#pragma unroll
                for (int e = 0; e < 4; e++) {
                    a1[e][2 * gq]     = bq.x;
                    a1[e][2 * gq + 1] = bq.y;
                }
            }

#pragma unroll
            for (int i = 0; i < NFEAT; i++) {
                float4 fv = *(const float4*)(fbl + i * H_R);   // 128B bcast, 1 wf
                u64 fe[4];
                fe[0] = pk2(fv.x, fv.x);
                fe[1] = pk2(fv.y, fv.y);
                fe[2] = pk2(fv.z, fv.z);
                fe[3] = pk2(fv.w, fv.w);
#pragma unroll
                for (int gq = 0; gq < 4; gq++) {
                    ulonglong2 w = W1l[i * 16 + 4 * gq];   // 64B-contig request
#pragma unroll
                    for (int e = 0; e < 4; e++) {
                        a1[e][2 * gq]     = ffma2(fe[e], w.x, a1[e][2 * gq]);
                        a1[e][2 * gq + 1] = ffma2(fe[e], w.y, a1[e][2 * gq + 1]);
                    }
                }
            }

            // tanh + transposed store: h2[u][elem], u = 16*gq + 4*l + j
#pragma unroll
            for (int gq = 0; gq < 4; gq++) {
                float tq[4][4];
#pragma unroll
                for (int e = 0; e < 4; e++) {
                    float x0, x1, x2, x3;
                    upk2(a1[e][2 * gq],     x0, x1);
                    upk2(a1[e][2 * gq + 1], x2, x3);
                    tq[e][0] = tanh_fast(x0);
                    tq[e][1] = tanh_fast(x1);
                    tq[e][2] = tanh_fast(x2);
                    tq[e][3] = tanh_fast(x3);
                }
#pragma unroll
                for (int j = 0; j < 4; j++) {
                    int u = 16 * gq + 4 * l + j;
                    *(float4*)(hbsl + u * H_R) =
                        make_float4(tq[0][j], tq[1][j], tq[2][j], tq[3][j]);
                }
            }
        }
        __syncwarp();

        // ---- layer 2: own 16 units over all 64 hidden, 4 elems ----
        // 2-stage pipeline with LINEAR prefetch: pointers only increment;
        // the k=63 prefetch reads the pad row (never consumed).
        u64 a2[4][8];
#pragma unroll
        for (int gq = 0; gq < 4; gq++) {
            ulonglong2 bq = B2l[4 * gq];
#pragma unroll
            for (int e = 0; e < 4; e++) {
                a2[e][2 * gq]     = bq.x;
                a2[e][2 * gq + 1] = bq.y;
            }
        }

        const float*      hp = hbl;
        const ulonglong2* Wp = W2l;
        float4     hv_n = *(const float4*)hp;
        ulonglong2 wn0  = Wp[0];
        ulonglong2 wn1  = Wp[4];
        ulonglong2 wn2  = Wp[8];
        ulonglong2 wn3  = Wp[12];

#pragma unroll 8
        for (int k = 0; k < HID; k++) {
            float4     hv = hv_n;
            ulonglong2 w0 = wn0, w1 = wn1, w2 = wn2, w3 = wn3;

            hp += H_R;
            Wp += 16;
            hv_n = *(const float4*)hp;
            wn0 = Wp[0]; wn1 = Wp[4]; wn2 = Wp[8]; wn3 = Wp[12];

            u64 hk0 = pk2(hv.x, hv.x);
            u64 hk1 = pk2(hv.y, hv.y);
            u64 hk2 = pk2(hv.z, hv.z);
            u64 hk3 = pk2(hv.w, hv.w);

            a2[0][0] = ffma2(hk0, w0.x, a2[0][0]);
            a2[0][1] = ffma2(hk0, w0.y, a2[0][1]);
            a2[1][0] = ffma2(hk1, w0.x, a2[1][0]);
            a2[1][1] = ffma2(hk1, w0.y, a2[1][1]);
            a2[2][0] = ffma2(hk2, w0.x, a2[2][0]);
            a2[2][1] = ffma2(hk2, w0.y, a2[2][1]);
            a2[3][0] = ffma2(hk3, w0.x, a2[3][0]);
            a2[3][1] = ffma2(hk3, w0.y, a2[3][1]);

            a2[0][2] = ffma2(hk0, w1.x, a2[0][2]);
            a2[0][3] = ffma2(hk0, w1.y, a2[0][3]);
            a2[1][2] = ffma2(hk1, w1.x, a2[1][2]);
            a2[1][3] = ffma2(hk1, w1.y, a2[1][3]);
            a2[2][2] = ffma2(hk2, w1.x, a2[2][2]);
            a2[2][3] = ffma2(hk2, w1.y, a2[2][3]);
            a2[3][2] = ffma2(hk3, w1.x, a2[3][2]);
            a2[3][3] = ffma2(hk3, w1.y, a2[3][3]);

            a2[0][4] = ffma2(hk0, w2.x, a2[0][4]);
            a2[0][5] = ffma2(hk0, w2.y, a2[0][5]);
            a2[1][4] = ffma2(hk1, w2.x, a2[1][4]);
            a2[1][5] = ffma2(hk1, w2.y, a2[1][5]);
            a2[2][4] = ffma2(hk2, w2.x, a2[2][4]);
            a2[2][5] = ffma2(hk2, w2.y, a2[2][5]);
            a2[3][4] = ffma2(hk3, w2.x, a2[3][4]);
            a2[3][5] = ffma2(hk3, w2.y, a2[3][5]);

            a2[0][6] = ffma2(hk0, w3.x, a2[0][6]);
            a2[0][7] = ffma2(hk0, w3.y, a2[0][7]);
            a2[1][6] = ffma2(hk1, w3.x, a2[1][6]);
            a2[1][7] = ffma2(hk1, w3.y, a2[1][7]);
            a2[2][6] = ffma2(hk2, w3.x, a2[2][6]);
            a2[2][7] = ffma2(hk2, w3.y, a2[2][7]);
            a2[3][6] = ffma2(hk3, w3.x, a2[3][6]);
            a2[3][7] = ffma2(hk3, w3.y, a2[3][7]);
        }
        __syncwarp();

        // ---- layer 3: partial dot over own 16 units, per element ----
        float sx[4], sy[4];
        {
            u64 c[4], d[4];
            u64 binit = (l == 0) ? pk2(sm[OFF_B3], sm[OFF_B3 + 1]) : pk2(0.0f, 0.0f);
#pragma unroll
            for (int e = 0; e < 4; e++) { c[e] = binit; d[e] = pk2(0.0f, 0.0f); }
#pragma unroll
            for (int gq = 0; gq < 4; gq++) {
                ulonglong2 wA = W3l[8 * gq];
                ulonglong2 wB = W3l[8 * gq + 1];
#pragma unroll
                for (int e = 0; e < 4; e++) {
                    float x0, x1, x2, x3;
                    upk2(a2[e][2 * gq],     x0, x1);
                    upk2(a2[e][2 * gq + 1], x2, x3);
                    float g0 = tanh_fast(x0), g1 = tanh_fast(x1);
                    float g2 = tanh_fast(x2), g3 = tanh_fast(x3);
                    c[e] = ffma2(pk2(g0, g0), wA.x, c[e]);
                    d[e] = ffma2(pk2(g1, g1), wA.y, d[e]);
                    c[e] = ffma2(pk2(g2, g2), wB.x, c[e]);
                    d[e] = ffma2(pk2(g3, g3), wB.y, d[e]);
                }
            }
#pragma unroll
            for (int e = 0; e < 4; e++) {
                float x0, y0, x1, y1;
                upk2(c[e], x0, y0); upk2(d[e], x1, y1);
                sx[e] = x0 + x1; sy[e] = y0 + y1;
            }
        }

        // ---- 2-stage transpose-reduce: lane l ends with element l's sum ----
        // Stage 1 (xor 1): keep elements with e&1 == par; send opposite parity.
        float k0x, k1x, k0y, k1y;
        {
            float s0x = par ? sx[0] : sx[1];   // send: partner's kept low elem
            float s1x = par ? sx[2] : sx[3];   // send: partner's kept high elem
            float s0y = par ? sy[0] : sy[1];
            float s1y = par ? sy[2] : sy[3];
            float r0x = __shfl_xor_sync(FULL, s0x, 1);
            float r1x = __shfl_xor_sync(FULL, s1x, 1);
            float r0y = __shfl_xor_sync(FULL, s0y, 1);
            float r1y = __shfl_xor_sync(FULL, s1y, 1);
            k0x = (par ? sx[1] : sx[0]) + r0x;   // e = par
            k1x = (par ? sx[3] : sx[2]) + r1x;   // e = par + 2
            k0y = (par ? sy[1] : sy[0]) + r0y;
            k1y = (par ? sy[3] : sy[2]) + r1y;
        }
        // Stage 2 (xor 2): keep e == l (= par + 2*hib); send the other.
        float corrx, corry;
        {
            float sxv = hib ? k0x : k1x;
            float syv = hib ? k0y : k1y;
            float rx  = __shfl_xor_sync(FULL, sxv, 2);
            float ry  = __shfl_xor_sync(FULL, syv, 2);
            corrx = ((hib ? k1x : k0x) + rx) * 0.1f;
            corry = ((hib ? k1y : k0y) + ry) * 0.1f;
        }

        // ---- integrate own element ----
        float a1x = corrx - fric * v1x;
        float a1y = g + corry - fric * v1y;
        float a2x = corrx - fric * v2x;
        float a2y = g + corry - fric * v2y;

        v1x += a1x * DT_F;  v1y += a1y * DT_F;
        v2x += a2x * DT_F;  v2y += a2y * DT_F;
        p1x += v1x * DT_F;  p1y += v1y * DT_F;
        p2x += v2x * DT_F;  p2y += v2y * DT_F;

        bool m;
        m = (p1x < 20.0f) || (p1x > 780.0f); v1x = m ? -0.8f * v1x : v1x;
        p1x = fminf(fmaxf(p1x, 20.0f), 780.0f);
        m = (p1y < 20.0f) || (p1y > 580.0f); v1y = m ? -0.8f * v1y : v1y;
        p1y = fminf(fmaxf(p1y, 20.0f), 580.0f);

        m = (p2x < 20.0f) || (p2x > 780.0f); v2x = m ? -0.8f * v2x : v2x;
        p2x = fminf(fmaxf(p2x, 20.0f), 780.0f);
        m = (p2y < 20.0f) || (p2y > 580.0f); v2y = m ? -0.8f * v2y : v2y;
        p2y = fminf(fmaxf(p2y, 20.0f), 580.0f);
    }
}

extern "C" void kernel_launch(void* const* d_in, const int* in_sizes, int n_in,
                              void* d_out, int out_size) {
    const float* inp  = (const float*)d_in[0];
    const float* W1   = (const float*)d_in[1];
    const float* b1   = (const float*)d_in[2];
    const float* W2   = (const float*)d_in[3];
    const float* b2   = (const float*)d_in[4];
    const float* W3   = (const float*)d_in[5];
    const float* b3   = (const float*)d_in[6];
    const float* grav = (const float*)d_in[7];
    const float* fric = (const float*)d_in[8];
    float* out = (float*)d_out;

    int nB = in_sizes[0] / (STEPS * 8);

    static int smem_set = 0;
    if (!smem_set) {
        cudaFuncSetAttribute(phys_kernel,
                             cudaFuncAttributeMaxDynamicSharedMemorySize, SM_BYTES);
        smem_set = 1;
    }

    int nElems = ((nB + 127) / 128) * 128;      // 128 elements per CTA
    int grid   = nElems / 128;
    phys_kernel<<<grid, TPB, SM_BYTES>>>(inp, W1, b1, W2, b2, W3, b3,
                                         grav, fric, out, nB);
}

// round 16
// speedup vs baseline: 1.0310x; 1.0139x over previous
#include <cuda_runtime.h>

// MinimalPhysicsModel: 50-step recurrent sim + MLP(11->64->64->2, tanh).
// CONVERGED KERNEL (= R13, best measured: 1475.5 us).
// S=4 lanes/slot, E=4 elements/slot. Interleaved quad ownership: every weight
// LDS.128 request is 64B-contiguous (1 wavefront); transposed h staging makes
// every layer-2 h load a 128B-contiguous broadcast (1 wavefront). Linear-
// prefetch software pipeline in layer-2, SMEM feature broadcast, fast
// polynomial atan2, 5-op tanh. TPB=128, 3 blocks/SM @ 168 regs (RF-full).

#define STEPS   50
#define HID     64
#define NFEAT   11
#define EPS_F   1e-6f
#define DT_F    (1.0f/30.0f)
#define TPB     128

typedef unsigned long long u64;

__device__ __forceinline__ u64 pk2(float x, float y) {
    u64 r; asm("mov.b64 %0,{%1,%2};" : "=l"(r) : "f"(x), "f"(y)); return r;
}
__device__ __forceinline__ void upk2(u64 v, float& x, float& y) {
    asm("mov.b64 {%0,%1},%2;" : "=f"(x), "=f"(y) : "l"(v));
}
__device__ __forceinline__ u64 ffma2(u64 a, u64 b, u64 c) {
    u64 d; asm("fma.rn.f32x2 %0,%1,%2,%3;" : "=l"(d) : "l"(a), "l"(b), "l"(c)); return d;
}

// tanh(x) = 1 - 2/(1 + e^{2x});  sign-correct, inf-safe, 5 ops, |err| ~1e-7.
__device__ __forceinline__ float tanh_fast(float x) {
    float e;
    asm("ex2.approx.f32 %0, %1;" : "=f"(e) : "f"(x * 2.885390082f)); // 2*log2(e)
    float rc;
    asm("rcp.approx.f32 %0, %1;" : "=f"(rc) : "f"(1.0f + e));
    return fmaf(-2.0f, rc, 1.0f);
}

__device__ __forceinline__ float sqrt_fast(float x) {
    float r;
    asm("sqrt.approx.f32 %0, %1;" : "=f"(r) : "f"(x));
    return r;
}

// atan2 via degree-11 odd minimax on [0,1] + octant fixups; |err| ~2e-7.
__device__ __forceinline__ float atan2_fast(float y, float x) {
    float ax = fabsf(x), ay = fabsf(y);
    float mx = fmaxf(ax, ay), mn = fminf(ax, ay);
    float r  = __fdividef(mn, mx);
    float q  = r * r;
    float p  = fmaf(q, -0.0117212f,  0.05265332f);
    p = fmaf(q, p, -0.11643287f);
    p = fmaf(q, p,  0.19354346f);
    p = fmaf(q, p, -0.33262347f);
    p = fmaf(q, p,  0.99997726f);
    float a = r * p;
    a = (ay > ax) ? (1.57079632679f - a) : a;
    a = (x < 0.0f) ? (3.14159265359f - a) : a;
    return copysignf(a, y);
}

// shared layout (floats)
#define OFF_W1  0        // 11*64 = 704
#define OFF_B1  704      // 64
#define OFF_W2  768      // 64*64 = 4096
#define OFF_B2  4864     // 64
#define OFF_W3  4928     // 64*2 = 128
#define OFF_B3  5056     // 2
#define OFF_H   5060     // h2[65][132]: 64 rows + 1 pad row (prefetch overrun)
#define H_R     132
#define OFF_F   (OFF_H + 65 * H_R)              // f2[11][132]
#define SM_FLOATS (OFF_F + NFEAT * H_R)         // 15092
#define SM_BYTES  (SM_FLOATS * 4)               // 60368  (x3 = 181KB/SM)

__global__ void __launch_bounds__(TPB, 3)
phys_kernel(const float* __restrict__ inp,
            const float* __restrict__ W1, const float* __restrict__ b1,
            const float* __restrict__ W2, const float* __restrict__ b2,
            const float* __restrict__ W3, const float* __restrict__ b3,
            const float* __restrict__ grav, const float* __restrict__ fricp,
            float* __restrict__ out, int nB)
{
    extern __shared__ __align__(16) float sm[];
    int tid = threadIdx.x;

    for (int i = tid; i < 704;  i += TPB) sm[OFF_W1 + i] = W1[i];
    for (int i = tid; i < 64;   i += TPB) sm[OFF_B1 + i] = b1[i];
    for (int i = tid; i < 4096; i += TPB) sm[OFF_W2 + i] = W2[i];
    for (int i = tid; i < 64;   i += TPB) sm[OFF_B2 + i] = b2[i];
    for (int i = tid; i < 128;  i += TPB) sm[OFF_W3 + i] = W3[i];
    if (tid == 0) { sm[OFF_B3] = b3[0]; sm[OFF_B3 + 1] = b3[1]; }
    __syncthreads();

    const int l      = tid & 3;            // owns row-quads {l, l+4, l+8, l+12}
    const int leBase = tid & ~3;           // CTA-local element base of this slot

    int myE = (blockIdx.x * 32 + (tid >> 2)) * 4 + l;
    if (myE >= nB) myE = nB - 1;           // dup-safe (identical writes)

    float p1x, p1y, p2x, p2y, v1x, v1y, v2x, v2y;
    {
        const float* s0 = inp + (size_t)myE * STEPS * 8;
        float4 a = *(const float4*)(s0);
        float4 b = *(const float4*)(s0 + 4);
        p1x = a.x; p1y = a.y; p2x = a.z; p2y = a.w;
        v1x = b.x; v1y = b.y; v2x = b.z; v2y = b.w;
    }

    float g    = grav[0] * 40.0f;
    float fric = fabsf(fricp[0]);

    float* ob = out + (size_t)myE * STEPS * 8;

    // lane-hoisted base pointers
    const ulonglong2* W1l  = (const ulonglong2*)(sm + OFF_W1) + l;     // [11][16]
    const ulonglong2* B1l  = (const ulonglong2*)(sm + OFF_B1) + l;     // [16]
    const ulonglong2* W2l  = (const ulonglong2*)(sm + OFF_W2) + l;     // [64][16]
    const ulonglong2* B2l  = (const ulonglong2*)(sm + OFF_B2) + l;     // [16]
    const ulonglong2* W3l  = (const ulonglong2*)(sm + OFF_W3) + 2 * l; // [32]
    const float*      hbl  = sm + OFF_H + leBase;
    float*            hbsl = sm + OFF_H + leBase;
    const float*      fbl  = sm + OFF_F + leBase;
    float*            fbs  = sm + OFF_F + tid;    // own element's feature column

    const unsigned FULL = 0xffffffffu;

#pragma unroll 1
    for (int t = 0; t < STEPS; t++) {
        *(float4*)(ob)     = make_float4(p1x, p1y, p2x, p2y);
        *(float4*)(ob + 4) = make_float4(v1x, v1y, v2x, v2y);
        ob += 8;

        // ---- features for own element -> SMEM transposed columns ----
        {
            float s1  = p1x * p1x + p1y * p1y;      // = r1^2
            float r1  = sqrt_fast(s1);
            float th1 = atan2_fast(p1y, p1x);
            float vr1 = __fdividef(p1x * v1x + p1y * v1y, r1 + EPS_F);
            float vt1 = __fdividef(p1x * v1y - p1y * v1x, s1 + EPS_F);
            float L1  = r1 * vt1;

            float s2  = p2x * p2x + p2y * p2y;      // = r2^2
            float r2  = sqrt_fast(s2);
            float th2 = atan2_fast(p2y, p2x);
            float vr2 = __fdividef(p2x * v2x + p2y * v2y, r2 + EPS_F);
            float vt2 = __fdividef(p2x * v2y - p2y * v2x, s2 + EPS_F);
            float L2  = r2 * vt2;

            float dx = p2x - p1x, dy = p2y - p1y;
            float r12 = sqrt_fast(dx * dx + dy * dy);

            fbs[0 * H_R]  = r1;  fbs[1 * H_R] = th1; fbs[2 * H_R] = vr1;
            fbs[3 * H_R]  = vt1; fbs[4 * H_R] = L1;  fbs[5 * H_R] = r2;
            fbs[6 * H_R]  = th2; fbs[7 * H_R] = vr2; fbs[8 * H_R] = vt2;
            fbs[9 * H_R]  = L2;  fbs[10 * H_R] = r12;
        }
        __syncwarp();

        // ---- layer 1: own 16 hidden units (interleaved quads) x 4 elems ----
        {
            u64 a1[4][8];
#pragma unroll
            for (int gq = 0; gq < 4; gq++) {
                ulonglong2 bq = B1l[4 * gq];
#pragma unroll
                for (int e = 0; e < 4; e++) {
                    a1[e][2 * gq]     = bq.x;
                    a1[e][2 * gq + 1] = bq.y;
                }
            }

#pragma unroll
            for (int i = 0; i < NFEAT; i++) {
                float4 fv = *(const float4*)(fbl + i * H_R);   // 128B bcast, 1 wf
                u64 fe[4];
                fe[0] = pk2(fv.x, fv.x);
                fe[1] = pk2(fv.y, fv.y);
                fe[2] = pk2(fv.z, fv.z);
                fe[3] = pk2(fv.w, fv.w);
#pragma unroll
                for (int gq = 0; gq < 4; gq++) {
                    ulonglong2 w = W1l[i * 16 + 4 * gq];   // 64B-contig request
#pragma unroll
                    for (int e = 0; e < 4; e++) {
                        a1[e][2 * gq]     = ffma2(fe[e], w.x, a1[e][2 * gq]);
                        a1[e][2 * gq + 1] = ffma2(fe[e], w.y, a1[e][2 * gq + 1]);
                    }
                }
            }

            // tanh + transposed store: h2[u][elem], u = 16*gq + 4*l + j
#pragma unroll
            for (int gq = 0; gq < 4; gq++) {
                float tq[4][4];
#pragma unroll
                for (int e = 0; e < 4; e++) {
                    float x0, x1, x2, x3;
                    upk2(a1[e][2 * gq],     x0, x1);
                    upk2(a1[e][2 * gq + 1], x2, x3);
                    tq[e][0] = tanh_fast(x0);
                    tq[e][1] = tanh_fast(x1);
                    tq[e][2] = tanh_fast(x2);
                    tq[e][3] = tanh_fast(x3);
                }
#pragma unroll
                for (int j = 0; j < 4; j++) {
                    int u = 16 * gq + 4 * l + j;
                    *(float4*)(hbsl + u * H_R) =
                        make_float4(tq[0][j], tq[1][j], tq[2][j], tq[3][j]);
                }
            }
        }
        __syncwarp();

        // ---- layer 2: own 16 units over all 64 hidden, 4 elems ----
        // 2-stage pipeline with LINEAR prefetch: pointers only increment;
        // the k=63 prefetch reads the pad row (never consumed).
        u64 a2[4][8];
#pragma unroll
        for (int gq = 0; gq < 4; gq++) {
            ulonglong2 bq = B2l[4 * gq];
#pragma unroll
            for (int e = 0; e < 4; e++) {
                a2[e][2 * gq]     = bq.x;
                a2[e][2 * gq + 1] = bq.y;
            }
        }

        const float*      hp = hbl;
        const ulonglong2* Wp = W2l;
        float4     hv_n = *(const float4*)hp;
        ulonglong2 wn0  = Wp[0];
        ulonglong2 wn1  = Wp[4];
        ulonglong2 wn2  = Wp[8];
        ulonglong2 wn3  = Wp[12];

#pragma unroll 8
        for (int k = 0; k < HID; k++) {
            float4     hv = hv_n;
            ulonglong2 w0 = wn0, w1 = wn1, w2 = wn2, w3 = wn3;

            hp += H_R;
            Wp += 16;
            hv_n = *(const float4*)hp;
            wn0 = Wp[0]; wn1 = Wp[4]; wn2 = Wp[8]; wn3 = Wp[12];

            u64 hk0 = pk2(hv.x, hv.x);
            u64 hk1 = pk2(hv.y, hv.y);
            u64 hk2 = pk2(hv.z, hv.z);
            u64 hk3 = pk2(hv.w, hv.w);

            a2[0][0] = ffma2(hk0, w0.x, a2[0][0]);
            a2[0][1] = ffma2(hk0, w0.y, a2[0][1]);
            a2[1][0] = ffma2(hk1, w0.x, a2[1][0]);
            a2[1][1] = ffma2(hk1, w0.y, a2[1][1]);
            a2[2][0] = ffma2(hk2, w0.x, a2[2][0]);
            a2[2][1] = ffma2(hk2, w0.y, a2[2][1]);
            a2[3][0] = ffma2(hk3, w0.x, a2[3][0]);
            a2[3][1] = ffma2(hk3, w0.y, a2[3][1]);

            a2[0][2] = ffma2(hk0, w1.x, a2[0][2]);
            a2[0][3] = ffma2(hk0, w1.y, a2[0][3]);
            a2[1][2] = ffma2(hk1, w1.x, a2[1][2]);
            a2[1][3] = ffma2(hk1, w1.y, a2[1][3]);
            a2[2][2] = ffma2(hk2, w1.x, a2[2][2]);
            a2[2][3] = ffma2(hk2, w1.y, a2[2][3]);
            a2[3][2] = ffma2(hk3, w1.x, a2[3][2]);
            a2[3][3] = ffma2(hk3, w1.y, a2[3][3]);

            a2[0][4] = ffma2(hk0, w2.x, a2[0][4]);
            a2[0][5] = ffma2(hk0, w2.y, a2[0][5]);
            a2[1][4] = ffma2(hk1, w2.x, a2[1][4]);
            a2[1][5] = ffma2(hk1, w2.y, a2[1][5]);
            a2[2][4] = ffma2(hk2, w2.x, a2[2][4]);
            a2[2][5] = ffma2(hk2, w2.y, a2[2][5]);
            a2[3][4] = ffma2(hk3, w2.x, a2[3][4]);
            a2[3][5] = ffma2(hk3, w2.y, a2[3][5]);

            a2[0][6] = ffma2(hk0, w3.x, a2[0][6]);
            a2[0][7] = ffma2(hk0, w3.y, a2[0][7]);
            a2[1][6] = ffma2(hk1, w3.x, a2[1][6]);
            a2[1][7] = ffma2(hk1, w3.y, a2[1][7]);
            a2[2][6] = ffma2(hk2, w3.x, a2[2][6]);
            a2[2][7] = ffma2(hk2, w3.y, a2[2][7]);
            a2[3][6] = ffma2(hk3, w3.x, a2[3][6]);
            a2[3][7] = ffma2(hk3, w3.y, a2[3][7]);
        }
        __syncwarp();

        // ---- layer 3: partial dot over own 16 units, per element ----
        u64 c[4], d[4];
        {
            u64 binit = (l == 0) ? pk2(sm[OFF_B3], sm[OFF_B3 + 1]) : pk2(0.0f, 0.0f);
#pragma unroll
            for (int e = 0; e < 4; e++) { c[e] = binit; d[e] = pk2(0.0f, 0.0f); }
#pragma unroll
            for (int gq = 0; gq < 4; gq++) {
                ulonglong2 wA = W3l[8 * gq];
                ulonglong2 wB = W3l[8 * gq + 1];
#pragma unroll
                for (int e = 0; e < 4; e++) {
                    float x0, x1, x2, x3;
                    upk2(a2[e][2 * gq],     x0, x1);
                    upk2(a2[e][2 * gq + 1], x2, x3);
                    float g0 = tanh_fast(x0), g1 = tanh_fast(x1);
                    float g2 = tanh_fast(x2), g3 = tanh_fast(x3);
                    c[e] = ffma2(pk2(g0, g0), wA.x, c[e]);
                    d[e] = ffma2(pk2(g1, g1), wA.y, d[e]);
                    c[e] = ffma2(pk2(g2, g2), wB.x, c[e]);
                    d[e] = ffma2(pk2(g3, g3), wB.y, d[e]);
                }
            }
        }

        // butterfly-reduce each element's partial across the 4 slot lanes
        float corrx = 0.0f, corry = 0.0f;
#pragma unroll
        for (int e = 0; e < 4; e++) {
            float x0, y0, x1, y1;
            upk2(c[e], x0, y0); upk2(d[e], x1, y1);
            float sx = x0 + x1, sy = y0 + y1;
            float u;
            u = __shfl_xor_sync(FULL, sx, 1); sx = sx + u;   // commutative: identical on all lanes
            u = __shfl_xor_sync(FULL, sx, 2); sx = sx + u;
            u = __shfl_xor_sync(FULL, sy, 1); sy = sy + u;
            u = __shfl_xor_sync(FULL, sy, 2); sy = sy + u;
            if (e == l) { corrx = sx * 0.1f; corry = sy * 0.1f; }
        }

        // ---- integrate own element ----
        float a1x = corrx - fric * v1x;
        float a1y = g + corry - fric * v1y;
        float a2x = corrx - fric * v2x;
        float a2y = g + corry - fric * v2y;

        v1x += a1x * DT_F;  v1y += a1y * DT_F;
        v2x += a2x * DT_F;  v2y += a2y * DT_F;
        p1x += v1x * DT_F;  p1y += v1y * DT_F;
        p2x += v2x * DT_F;  p2y += v2y * DT_F;

        bool m;
        m = (p1x < 20.0f) || (p1x > 780.0f); v1x = m ? -0.8f * v1x : v1x;
        p1x = fminf(fmaxf(p1x, 20.0f), 780.0f);
        m = (p1y < 20.0f) || (p1y > 580.0f); v1y = m ? -0.8f * v1y : v1y;
        p1y = fminf(fmaxf(p1y, 20.0f), 580.0f);

        m = (p2x < 20.0f) || (p2x > 780.0f); v2x = m ? -0.8f * v2x : v2x;
        p2x = fminf(fmaxf(p2x, 20.0f), 780.0f);
        m = (p2y < 20.0f) || (p2y > 580.0f); v2y = m ? -0.8f * v2y : v2y;
        p2y = fminf(fmaxf(p2y, 20.0f), 580.0f);
    }
}

extern "C" void kernel_launch(void* const* d_in, const int* in_sizes, int n_in,
                              void* d_out, int out_size) {
    const float* inp  = (const float*)d_in[0];
    const float* W1   = (const float*)d_in[1];
    const float* b1   = (const float*)d_in[2];
    const float* W2   = (const float*)d_in[3];
    const float* b2   = (const float*)d_in[4];
    const float* W3   = (const float*)d_in[5];
    const float* b3   = (const float*)d_in[6];
    const float* grav = (const float*)d_in[7];
    const float* fric = (const float*)d_in[8];
    float* out = (float*)d_out;

    int nB = in_sizes[0] / (STEPS * 8);

    static int smem_set = 0;
    if (!smem_set) {
        cudaFuncSetAttribute(phys_kernel,
                             cudaFuncAttributeMaxDynamicSharedMemorySize, SM_BYTES);
        smem_set = 1;
    }

    int nElems = ((nB + 127) / 128) * 128;      // 128 elements per CTA
    int grid   = nElems / 128;
    phys_kernel<<<grid, TPB, SM_BYTES>>>(inp, W1, b1, W2, b2, W3, b3,
                                         grav, fric, out, nB);
}